// round 16
// baseline (speedup 1.0000x reference)
#include <cuda_runtime.h>
#include <stdint.h>
#include <math.h>

#define NN   256
#define CZ   128
#define H    4
#define DH   32
#define NPOS (NN*NN)
#define LOG2E 1.4426950408889634f

// Scratch (device globals; device-code access only).
__device__ __align__(16) uint32_t g_xn[NPOS*CZ];   // A-frag layout [mtile][ktile][128]
__device__ __align__(16) uint32_t g_q [NPOS*CZ];   // row-major tf32
__device__ __align__(16) uint32_t g_k [NPOS*CZ];   // row-major tf32
__device__ __align__(16) uint32_t g_v [NPOS*CZ];   // row-major tf32
__device__ __align__(16) float    g_g [NPOS*CZ];   // gates row-major fp32
__device__ __align__(16) uint32_t g_o [NPOS*CZ];   // row-major tf32 (attn out)
__device__ __align__(16) uint32_t g_oa[NPOS*CZ];   // A-frag layout (for k_outp)
__device__ __align__(16) float    g_tri [H*NPOS];  // tri * log2e
__device__ __align__(16) float    g_trif[H*NPOS];  // fragment-permuted tri (perm-key)
__device__ __align__(16) uint32_t g_wt[5*CZ*CZ];   // weights B-frag layout

// ---- helpers ---------------------------------------------------------------
__device__ __forceinline__ uint32_t f2tf32(float f) {
    uint32_t u;
    asm("cvt.rna.tf32.f32 %0, %1;" : "=r"(u) : "f"(f));
    return u;
}
__device__ __forceinline__ float ex2f(float x) {
    float y;
    asm("ex2.approx.f32 %0, %1;" : "=f"(y) : "f"(x));
    return y;
}
__device__ __forceinline__ void mma_tf32(float* d, const uint32_t* a, const uint32_t* b) {
    asm volatile(
        "mma.sync.aligned.m16n8k8.row.col.f32.tf32.tf32.f32 "
        "{%0,%1,%2,%3}, {%4,%5,%6,%7}, {%8,%9}, {%0,%1,%2,%3};"
        : "+f"(d[0]), "+f"(d[1]), "+f"(d[2]), "+f"(d[3])
        : "r"(a[0]), "r"(a[1]), "r"(a[2]), "r"(a[3]),
          "r"(b[0]), "r"(b[1]));
}
__device__ __forceinline__ void cp16(uint32_t* smem_dst, const uint32_t* gsrc) {
    uint32_t sa = (uint32_t)__cvta_generic_to_shared(smem_dst);
    asm volatile("cp.async.ca.shared.global [%0], [%1], 16;"
                 :: "r"(sa), "l"(gsrc) : "memory");
}
#define CP_COMMIT() asm volatile("cp.async.commit_group;" ::: "memory")
#define CP_WAIT0()  asm volatile("cp.async.wait_group 0;" ::: "memory")

// B-frag word index: tile (8 n x 8 k) = 64 contiguous words.
__device__ __forceinline__ int wfrag(int o, int c) {
    return (((o>>3)*16 + (c>>3))<<6) + (((o&7)*4 + (c&3))<<1) + ((c>>2)&1);
}

// ---------------------------------------------------------------------------
// K1: LayerNorm (warp per position, 16 rows/block) + tri bias.
// ---------------------------------------------------------------------------
__global__ __launch_bounds__(512) void k_ln(
    const float* __restrict__ x,
    const float* __restrict__ ln_g,
    const float* __restrict__ ln_b,
    const float* __restrict__ w_tri)
{
    __shared__ float ys[16][132];
    int warp = threadIdx.x >> 5;
    int lane = threadIdx.x & 31;
    int pos  = blockIdx.x * 16 + warp;

    float4 v = *(const float4*)(x + (size_t)pos*CZ + lane*4);
    float s  = v.x + v.y + v.z + v.w;
    float ss = v.x*v.x + v.y*v.y + v.z*v.z + v.w*v.w;
    #pragma unroll
    for (int off = 16; off; off >>= 1) {
        s  += __shfl_xor_sync(0xffffffffu, s,  off);
        ss += __shfl_xor_sync(0xffffffffu, ss, off);
    }
    float mu  = s * (1.0f/CZ);
    float var = ss * (1.0f/CZ) - mu*mu;
    float rs  = rsqrtf(var + 1e-5f);

    float4 gg = *(const float4*)(ln_g + lane*4);
    float4 bb = *(const float4*)(ln_b + lane*4);
    float4 y;
    y.x = (v.x - mu)*rs*gg.x + bb.x;
    y.y = (v.y - mu)*rs*gg.y + bb.y;
    y.z = (v.z - mu)*rs*gg.z + bb.z;
    y.w = (v.w - mu)*rs*gg.w + bb.w;
    *(float4*)&ys[warp][lane*4] = y;

    #pragma unroll
    for (int h = 0; h < H; h++) {
        float4 w = *(const float4*)(w_tri + h*CZ + lane*4);
        float d = y.x*w.x + y.y*w.y + y.z*w.z + y.w*w.w;
        #pragma unroll
        for (int off = 16; off; off >>= 1)
            d += __shfl_xor_sync(0xffffffffu, d, off);
        if (lane == 0) g_tri[h*NPOS + pos] = d * LOG2E;
    }
    __syncthreads();

    int kt = warp;
    int gq = lane >> 2, tq = lane & 3;
    int c0 = kt*8 + tq;
    uint4 u;
    u.x = f2tf32(ys[gq  ][c0  ]);
    u.y = f2tf32(ys[gq+8][c0  ]);
    u.z = f2tf32(ys[gq  ][c0+4]);
    u.w = f2tf32(ys[gq+8][c0+4]);
    *(uint4*)(g_xn + ((size_t)blockIdx.x*16 + kt)*128 + lane*4) = u;
}

// ---------------------------------------------------------------------------
// K_aux: weight prep (blocks 0..319) + tri fragment permute (320..575).
// Perm-key tri layout: thread (gq,tq) gets cols (tq, tq+4) of rows (q0, q0+8).
// ---------------------------------------------------------------------------
__global__ __launch_bounds__(256) void k_aux(
    const float* __restrict__ wq, const float* __restrict__ wk,
    const float* __restrict__ wv, const float* __restrict__ wg,
    const float* __restrict__ wo)
{
    if (blockIdx.x < 320) {
        int idx = blockIdx.x * 256 + threadIdx.x;
        int sel = idx >> 14;
        int rem = idx & 16383;
        int o = rem >> 7, c = rem & 127;
        const float* src = (sel==0) ? wq : (sel==1) ? wk : (sel==2) ? wv
                         : (sel==3) ? wg : wo;
        float v = src[rem];
        if (sel == 0) v *= 0.17677669529663687f * LOG2E;
        g_wt[sel*CZ*CZ + wfrag(o, c)] = f2tf32(v);
    } else {
        int wid  = (blockIdx.x - 320) * 8 + (threadIdx.x >> 5);
        int lane = threadIdx.x & 31;
        int h     = wid >> 9;
        int tile  = wid & 511;
        int mtile = tile >> 5;
        int jtile = tile & 31;
        int q0 = mtile*16 + (lane >> 2);
        int j0 = jtile*8  + (lane & 3);
        const float* tr = g_tri + (size_t)h*NPOS;
        float4 o;
        o.x = tr[(size_t)q0*NN + j0];
        o.y = tr[(size_t)q0*NN + j0 + 4];
        o.z = tr[(size_t)(q0+8)*NN + j0];
        o.w = tr[(size_t)(q0+8)*NN + j0 + 4];
        *(float4*)(g_trif + ((size_t)wid*32 + lane)*4) = o;
    }
}

// ---------------------------------------------------------------------------
// K_operm: g_o row-major -> g_oa A-frag layout.
// ---------------------------------------------------------------------------
__global__ __launch_bounds__(256) void k_operm()
{
    int wid  = blockIdx.x * 8 + (threadIdx.x >> 5);
    int lane = threadIdx.x & 31;
    int mt = wid >> 4, kt = wid & 15;
    int gq = lane >> 2, tq = lane & 3;
    int row = mt*16 + gq;
    int col = kt*8 + tq;
    uint4 u;
    u.x = g_o[(size_t)row*CZ + col];
    u.y = g_o[(size_t)(row+8)*CZ + col];
    u.z = g_o[(size_t)row*CZ + col+4];
    u.w = g_o[(size_t)(row+8)*CZ + col+4];
    *(uint4*)(g_oa + (size_t)wid*128 + lane*4) = u;
}

// ---------------------------------------------------------------------------
// Hybrid tf32 GEMM (r13-verified).
// ---------------------------------------------------------------------------
#define ACHUNK 4096
#define WCHUNK 4096

__device__ __forceinline__ void gemm_stage(
    const uint32_t* __restrict__ A, const uint32_t* __restrict__ W,
    uint32_t* as, uint32_t* ws, int mt0, int c, int t)
{
    #pragma unroll
    for (int i = 0; i < 4; i++) {
        int idx = t + i*256;
        int tile = idx >> 5;
        int off  = (idx & 31) * 4;
        int mt = tile >> 2, ktl = tile & 3;
        cp16(as + tile*128 + off,
             A + ((size_t)(mt0+mt)*16 + c*4 + ktl)*128 + off);
    }
    #pragma unroll
    for (int i = 0; i < 4; i++) {
        int idx = t + i*256;
        int tile = idx >> 4;
        int off  = (idx & 15) * 4;
        int nt = tile >> 2, ktl = tile & 3;
        cp16(ws + tile*64 + off,
             W + ((size_t)nt*16 + c*4 + ktl)*64 + off);
    }
}

__device__ __forceinline__ void gemm2(
    const uint32_t* __restrict__ A,
    const uint32_t* __restrict__ W,
    int sel, int p0,
    const float* __restrict__ bias,
    float* __restrict__ outf)
{
    extern __shared__ uint32_t dyn[];
    int t    = threadIdx.x;
    int warp = t >> 5;
    int lane = t & 31;
    int gq   = lane >> 2, tq = lane & 3;
    int wm   = (warp >> 2) * 64;
    int wn   = (warp & 3) * 32;
    int wmt  = (warp >> 2) * 4;
    int wnt  = (warp & 3) * 4;
    int mt0  = p0 >> 4;

    float acc[4][4][4];
    #pragma unroll
    for (int mi = 0; mi < 4; mi++)
        #pragma unroll
        for (int ni = 0; ni < 4; ni++)
            #pragma unroll
            for (int r = 0; r < 4; r++) acc[mi][ni][r] = 0.0f;

    gemm_stage(A, W, dyn, dyn + 2*ACHUNK, mt0, 0, t);
    CP_COMMIT();
    CP_WAIT0();
    __syncthreads();

    for (int c = 0; c < 4; c++) {
        if (c < 3) {
            int nb = (c+1) & 1;
            gemm_stage(A, W, dyn + nb*ACHUNK, dyn + 2*ACHUNK + nb*WCHUNK,
                       mt0, c+1, t);
            CP_COMMIT();
        }
        const uint32_t* as = dyn + (c&1)*ACHUNK;
        const uint32_t* ws = dyn + 2*ACHUNK + (c&1)*WCHUNK;

        #pragma unroll
        for (int ktl = 0; ktl < 4; ktl++) {
            uint4 a4[4];
            uint2 b2[4];
            #pragma unroll
            for (int mi = 0; mi < 4; mi++)
                a4[mi] = *(const uint4*)(as + ((wmt+mi)*4 + ktl)*128 + lane*4);
            #pragma unroll
            for (int ni = 0; ni < 4; ni++)
                b2[ni] = *(const uint2*)(ws + ((wnt+ni)*4 + ktl)*64 + lane*2);
            #pragma unroll
            for (int mi = 0; mi < 4; mi++)
                #pragma unroll
                for (int ni = 0; ni < 4; ni++)
                    mma_tf32(acc[mi][ni], (const uint32_t*)&a4[mi],
                             (const uint32_t*)&b2[ni]);
        }
        if (c < 3) {
            CP_WAIT0();
            __syncthreads();
        }
    }

    #pragma unroll
    for (int mi = 0; mi < 4; mi++) {
        #pragma unroll
        for (int ni = 0; ni < 4; ni++) {
            int col = wn + ni*8 + tq*2;
            int r0  = p0 + wm + mi*16 + gq;
            if (sel <= 2) {
                uint32_t* outt = (sel==0) ? g_q : (sel==1) ? g_k : g_v;
                #pragma unroll
                for (int rr = 0; rr < 2; rr++) {
                    int pos = r0 + rr*8;
                    *(uint2*)(outt + (size_t)pos*CZ + col) =
                        make_uint2(f2tf32(acc[mi][ni][rr*2+0]),
                                   f2tf32(acc[mi][ni][rr*2+1]));
                }
            } else if (sel == 3) {
                float b0 = bias[col], b1 = bias[col+1];
                #pragma unroll
                for (int rr = 0; rr < 2; rr++) {
                    int pos = r0 + rr*8;
                    float vx = 1.0f/(1.0f + __expf(-(acc[mi][ni][rr*2+0] + b0)));
                    float vy = 1.0f/(1.0f + __expf(-(acc[mi][ni][rr*2+1] + b1)));
                    *(float2*)(g_g + (size_t)pos*CZ + col) = make_float2(vx, vy);
                }
            } else {
                float b0 = bias[col], b1 = bias[col+1];
                #pragma unroll
                for (int rr = 0; rr < 2; rr++) {
                    int pos = r0 + rr*8;
                    *(float2*)(outf + (size_t)pos*CZ + col) =
                        make_float2(acc[mi][ni][rr*2+0] + b0,
                                    acc[mi][ni][rr*2+1] + b1);
                }
            }
        }
    }
}

__global__ __launch_bounds__(256, 2) void k_proj(const float* __restrict__ bg)
{
    int sel = blockIdx.y;
    gemm2(g_xn, g_wt + sel*CZ*CZ, sel, blockIdx.x * 128, bg, nullptr);
}

__global__ __launch_bounds__(256, 2) void k_outp(
    const float* __restrict__ bo, float* __restrict__ out)
{
    gemm2(g_oa, g_wt + 4*CZ*CZ, 4, blockIdx.x * 128, bo, out);
}

// ---------------------------------------------------------------------------
// K3: attention v7 — 256-thread CTA (8 warps, all 256 q-rows), grid (NN, H).
// Shuffle-free permuted-key PV; raw-fp32 P into mma (HW tf32 truncation),
// l accumulates the same raw p. K/V staged once per CTA for 8 warps.
// ---------------------------------------------------------------------------
#define KVSTG (64*36)

__global__ __launch_bounds__(256, 2) void k_attn(const float* __restrict__ mask)
{
    __shared__ uint32_t kvbuf[4*KVSTG];
    __shared__ float mb_s[256];

    int i  = blockIdx.x;
    int h  = blockIdx.y;
    int t = threadIdx.x;
    int warp = t >> 5, lane = t & 31;
    int gq = lane >> 2, tq = lane & 3;
    int wrow = warp * 32;                            // 8 warps cover 256 rows
    int pg = (gq & 1) ? (gq >> 1) + 4 : (gq >> 1);   // permuted key row

    mb_s[t] = LOG2E * 1e9f * (mask[i*NN + t] - 1.0f);

    uint32_t* kb[2] = { kvbuf,           kvbuf + KVSTG };
    uint32_t* vb[2] = { kvbuf + 2*KVSTG, kvbuf + 3*KVSTG };

    #pragma unroll
    for (int it = 0; it < 2; it++) {
        int idx = t + it*256;                        // 0..511
        int row = idx >> 3, c4 = idx & 7;
        size_t gb = ((size_t)(i*NN + row))*CZ + h*DH + c4*4;
        cp16(&kb[0][row*36 + c4*4], g_k + gb);
        cp16(&vb[0][row*36 + c4*4], g_v + gb);
    }
    CP_COMMIT();

    uint32_t qf[2][4][4];
    #pragma unroll
    for (int mi = 0; mi < 2; mi++) {
        const uint32_t* qr0 = g_q + ((size_t)(i*NN + wrow + mi*16 + gq))*CZ + h*DH;
        const uint32_t* qr8 = qr0 + 8*CZ;
        #pragma unroll
        for (int ks = 0; ks < 4; ks++) {
            qf[mi][ks][0] = qr0[ks*8 + tq];
            qf[mi][ks][1] = qr8[ks*8 + tq];
            qf[mi][ks][2] = qr0[ks*8 + tq + 4];
            qf[mi][ks][3] = qr8[ks*8 + tq + 4];
        }
    }

    float lrun[2][2] = {{0.f,0.f},{0.f,0.f}};
    float oacc[2][4][4];
    #pragma unroll
    for (int mi = 0; mi < 2; mi++)
        #pragma unroll
        for (int nd = 0; nd < 4; nd++)
            #pragma unroll
            for (int r = 0; r < 4; r++) oacc[mi][nd][r] = 0.0f;

    int mtile0 = wrow >> 4;
    const float4* tf = (const float4*)g_trif;

    CP_WAIT0();
    __syncthreads();

    for (int jb = 0; jb < 4; jb++) {
        int j0 = jb * 64;
        int cur = jb & 1;
        if (jb < 3) {
            int nxt = (jb+1) & 1;
            #pragma unroll
            for (int it = 0; it < 2; it++) {
                int idx = t + it*256;
                int row = idx >> 3, c4 = idx & 7;
                size_t gb = ((size_t)(i*NN + j0 + 64 + row))*CZ + h*DH + c4*4;
                cp16(&kb[nxt][row*36 + c4*4], g_k + gb);
                cp16(&vb[nxt][row*36 + c4*4], g_v + gb);
            }
            CP_COMMIT();
        }
        const uint32_t* k_s = kb[cur];
        const uint32_t* v_s = vb[cur];

        #pragma unroll
        for (int half = 0; half < 2; half++) {
            int jh = half * 32;

            // S = Q K^T with permuted key rows
            float sacc[2][4][4];
            #pragma unroll
            for (int mi = 0; mi < 2; mi++)
                #pragma unroll
                for (int ni = 0; ni < 4; ni++)
                    #pragma unroll
                    for (int r = 0; r < 4; r++) sacc[mi][ni][r] = 0.0f;

            #pragma unroll
            for (int ks = 0; ks < 4; ks++) {
                uint32_t bf[4][2];
                #pragma unroll
                for (int ni = 0; ni < 4; ni++) {
                    int base = (jh + ni*8 + pg)*36 + ks*8 + tq;
                    bf[ni][0] = k_s[base];
                    bf[ni][1] = k_s[base + 4];
                }
                #pragma unroll
                for (int mi = 0; mi < 2; mi++)
                    #pragma unroll
                    for (int ni = 0; ni < 4; ni++)
                        mma_tf32(sacc[mi][ni], qf[mi][ks], bf[ni]);
            }

            // p = ex2(sacc + tri + mb); raw fp32 p kept (HW truncates in mma)
            #pragma unroll
            for (int mi = 0; mi < 2; mi++) {
                float la0 = 0.f, la1 = 0.f;
                #pragma unroll
                for (int ni = 0; ni < 4; ni++) {
                    int jtile = jb*8 + half*4 + ni;
                    float4 tv = tf[((h*16 + mtile0 + mi)*32 + jtile)*32 + lane];
                    int j = j0 + jh + ni*8 + tq;
                    float mb0 = mb_s[j], mb1 = mb_s[j+4];
                    float p0 = ex2f(sacc[mi][ni][0] + (tv.x + mb0));
                    float p1 = ex2f(sacc[mi][ni][1] + (tv.y + mb1));
                    float p2 = ex2f(sacc[mi][ni][2] + (tv.z + mb0));
                    float p3 = ex2f(sacc[mi][ni][3] + (tv.w + mb1));
                    sacc[mi][ni][0] = p0;
                    sacc[mi][ni][1] = p1;
                    sacc[mi][ni][2] = p2;
                    sacc[mi][ni][3] = p3;
                    la0 += p0 + p1;
                    la1 += p2 + p3;
                }
                lrun[mi][0] += la0; lrun[mi][1] += la1;
            }

            // O += P V : A-frag = {c0, c2, c1, c3}, no shuffles
            #pragma unroll
            for (int ks2 = 0; ks2 < 4; ks2++) {
                uint32_t bf[4][2];
                #pragma unroll
                for (int nd = 0; nd < 4; nd++) {
                    bf[nd][0] = v_s[(jh + ks2*8 + tq)*36     + nd*8 + gq];
                    bf[nd][1] = v_s[(jh + ks2*8 + tq + 4)*36 + nd*8 + gq];
                }
                #pragma unroll
                for (int mi = 0; mi < 2; mi++) {
                    uint32_t af[4];
                    af[0] = __float_as_uint(sacc[mi][ks2][0]);
                    af[1] = __float_as_uint(sacc[mi][ks2][2]);
                    af[2] = __float_as_uint(sacc[mi][ks2][1]);
                    af[3] = __float_as_uint(sacc[mi][ks2][3]);
                    #pragma unroll
                    for (int nd = 0; nd < 4; nd++)
                        mma_tf32(oacc[mi][nd], af, bf[nd]);
                }
            }
        }
        if (jb < 3) {
            CP_WAIT0();
            __syncthreads();
        }
    }

    // epilogue: normalize, gate, store tf32 row-major
    #pragma unroll
    for (int mi = 0; mi < 2; mi++) {
        float l0 = lrun[mi][0];
        l0 += __shfl_xor_sync(0xffffffffu, l0, 1);
        l0 += __shfl_xor_sync(0xffffffffu, l0, 2);
        float l1 = lrun[mi][1];
        l1 += __shfl_xor_sync(0xffffffffu, l1, 1);
        l1 += __shfl_xor_sync(0xffffffffu, l1, 2);
        float inv0 = 1.0f / l0, inv1 = 1.0f / l1;
        int r0 = wrow + mi*16 + gq;
        #pragma unroll
        for (int nd = 0; nd < 4; nd++) {
            int d = h*DH + nd*8 + tq*2;
            size_t b0 = ((size_t)(i*NN + r0))*CZ + d;
            size_t b1 = ((size_t)(i*NN + r0 + 8))*CZ + d;
            float2 gg0 = *(const float2*)(g_g + b0);
            float2 gg1 = *(const float2*)(g_g + b1);
            *(uint2*)(g_o + b0) = make_uint2(
                f2tf32(oacc[mi][nd][0]*inv0*gg0.x),
                f2tf32(oacc[mi][nd][1]*inv0*gg0.y));
            *(uint2*)(g_o + b1) = make_uint2(
                f2tf32(oacc[mi][nd][2]*inv1*gg1.x),
                f2tf32(oacc[mi][nd][3]*inv1*gg1.y));
        }
    }
}

// ---------------------------------------------------------------------------
extern "C" void kernel_launch(void* const* d_in, const int* in_sizes, int n_in,
                              void* d_out, int out_size)
{
    const float* x     = (const float*)d_in[0];
    const float* mask  = (const float*)d_in[1];
    const float* ln_g  = (const float*)d_in[2];
    const float* ln_b  = (const float*)d_in[3];
    const float* w_tri = (const float*)d_in[4];
    const float* wq    = (const float*)d_in[5];
    const float* wk    = (const float*)d_in[6];
    const float* wv    = (const float*)d_in[7];
    const float* wg    = (const float*)d_in[8];
    const float* bg    = (const float*)d_in[9];
    const float* wo    = (const float*)d_in[10];
    const float* bo    = (const float*)d_in[11];
    float* out = (float*)d_out;

    const int GEMM_SMEM = (2*ACHUNK + 2*WCHUNK) * 4;   // 65536 B
    cudaFuncSetAttribute(k_proj, cudaFuncAttributeMaxDynamicSharedMemorySize, GEMM_SMEM);
    cudaFuncSetAttribute(k_outp, cudaFuncAttributeMaxDynamicSharedMemorySize, GEMM_SMEM);

    k_ln  <<<NPOS/16, 512>>>(x, ln_g, ln_b, w_tri);
    k_aux <<<576, 256>>>(wq, wk, wv, wg, wo);
    k_proj<<<dim3(NPOS/128, 4), 256, GEMM_SMEM>>>(bg);
    k_attn<<<dim3(NN, H), 256>>>(mask);
    k_operm<<<65536/8, 256>>>();
    k_outp<<<NPOS/128, 256, GEMM_SMEM>>>(bo, out);
}

// round 17
// speedup vs baseline: 1.0703x; 1.0703x over previous
#include <cuda_runtime.h>
#include <stdint.h>
#include <math.h>

#define NN   256
#define CZ   128
#define H    4
#define DH   32
#define NPOS (NN*NN)
#define LOG2E 1.4426950408889634f

// Scratch (device globals; device-code access only).
__device__ __align__(16) uint32_t g_xn[NPOS*CZ];   // A-frag layout [mtile][ktile][128]
__device__ __align__(16) uint32_t g_q [NPOS*CZ];   // row-major tf32
__device__ __align__(16) uint32_t g_k [NPOS*CZ];   // row-major tf32
__device__ __align__(16) uint32_t g_v [NPOS*CZ];   // row-major tf32
__device__ __align__(16) float    g_g [NPOS*CZ];   // gates row-major fp32
__device__ __align__(16) uint32_t g_oa[NPOS*CZ];   // attn out, A-frag layout
__device__ __align__(16) float    g_tri [H*NPOS];  // tri * log2e
__device__ __align__(16) float    g_trif[H*NPOS];  // fragment-permuted tri (perm-key)
__device__ __align__(16) uint32_t g_wt[5*CZ*CZ];   // weights B-frag layout

// ---- helpers ---------------------------------------------------------------
__device__ __forceinline__ uint32_t f2tf32(float f) {
    uint32_t u;
    asm("cvt.rna.tf32.f32 %0, %1;" : "=r"(u) : "f"(f));
    return u;
}
__device__ __forceinline__ float ex2f(float x) {
    float y;
    asm("ex2.approx.f32 %0, %1;" : "=f"(y) : "f"(x));
    return y;
}
__device__ __forceinline__ void mma_tf32(float* d, const uint32_t* a, const uint32_t* b) {
    asm volatile(
        "mma.sync.aligned.m16n8k8.row.col.f32.tf32.tf32.f32 "
        "{%0,%1,%2,%3}, {%4,%5,%6,%7}, {%8,%9}, {%0,%1,%2,%3};"
        : "+f"(d[0]), "+f"(d[1]), "+f"(d[2]), "+f"(d[3])
        : "r"(a[0]), "r"(a[1]), "r"(a[2]), "r"(a[3]),
          "r"(b[0]), "r"(b[1]));
}
__device__ __forceinline__ void cp16(uint32_t* smem_dst, const uint32_t* gsrc) {
    uint32_t sa = (uint32_t)__cvta_generic_to_shared(smem_dst);
    asm volatile("cp.async.ca.shared.global [%0], [%1], 16;"
                 :: "r"(sa), "l"(gsrc) : "memory");
}
#define CP_COMMIT() asm volatile("cp.async.commit_group;" ::: "memory")
#define CP_WAIT0()  asm volatile("cp.async.wait_group 0;" ::: "memory")

// B-frag word index: tile (8 n x 8 k) = 64 contiguous words.
__device__ __forceinline__ int wfrag(int o, int c) {
    return (((o>>3)*16 + (c>>3))<<6) + (((o&7)*4 + (c&3))<<1) + ((c>>2)&1);
}

// ---------------------------------------------------------------------------
// K1: LayerNorm (warp per position, 16 rows/block) + tri bias.
// ---------------------------------------------------------------------------
__global__ __launch_bounds__(512) void k_ln(
    const float* __restrict__ x,
    const float* __restrict__ ln_g,
    const float* __restrict__ ln_b,
    const float* __restrict__ w_tri)
{
    __shared__ float ys[16][132];
    int warp = threadIdx.x >> 5;
    int lane = threadIdx.x & 31;
    int pos  = blockIdx.x * 16 + warp;

    float4 v = *(const float4*)(x + (size_t)pos*CZ + lane*4);
    float s  = v.x + v.y + v.z + v.w;
    float ss = v.x*v.x + v.y*v.y + v.z*v.z + v.w*v.w;
    #pragma unroll
    for (int off = 16; off; off >>= 1) {
        s  += __shfl_xor_sync(0xffffffffu, s,  off);
        ss += __shfl_xor_sync(0xffffffffu, ss, off);
    }
    float mu  = s * (1.0f/CZ);
    float var = ss * (1.0f/CZ) - mu*mu;
    float rs  = rsqrtf(var + 1e-5f);

    float4 gg = *(const float4*)(ln_g + lane*4);
    float4 bb = *(const float4*)(ln_b + lane*4);
    float4 y;
    y.x = (v.x - mu)*rs*gg.x + bb.x;
    y.y = (v.y - mu)*rs*gg.y + bb.y;
    y.z = (v.z - mu)*rs*gg.z + bb.z;
    y.w = (v.w - mu)*rs*gg.w + bb.w;
    *(float4*)&ys[warp][lane*4] = y;

    #pragma unroll
    for (int h = 0; h < H; h++) {
        float4 w = *(const float4*)(w_tri + h*CZ + lane*4);
        float d = y.x*w.x + y.y*w.y + y.z*w.z + y.w*w.w;
        #pragma unroll
        for (int off = 16; off; off >>= 1)
            d += __shfl_xor_sync(0xffffffffu, d, off);
        if (lane == 0) g_tri[h*NPOS + pos] = d * LOG2E;
    }
    __syncthreads();

    int kt = warp;
    int gq = lane >> 2, tq = lane & 3;
    int c0 = kt*8 + tq;
    uint4 u;
    u.x = f2tf32(ys[gq  ][c0  ]);
    u.y = f2tf32(ys[gq+8][c0  ]);
    u.z = f2tf32(ys[gq  ][c0+4]);
    u.w = f2tf32(ys[gq+8][c0+4]);
    *(uint4*)(g_xn + ((size_t)blockIdx.x*16 + kt)*128 + lane*4) = u;
}

// ---------------------------------------------------------------------------
// K_aux: weight prep (blocks 0..319) + tri fragment permute (320..575).
// Perm-key tri layout: thread (gq,tq) gets cols (tq, tq+4) of rows (q0, q0+8).
// ---------------------------------------------------------------------------
__global__ __launch_bounds__(256) void k_aux(
    const float* __restrict__ wq, const float* __restrict__ wk,
    const float* __restrict__ wv, const float* __restrict__ wg,
    const float* __restrict__ wo)
{
    if (blockIdx.x < 320) {
        int idx = blockIdx.x * 256 + threadIdx.x;
        int sel = idx >> 14;
        int rem = idx & 16383;
        int o = rem >> 7, c = rem & 127;
        const float* src = (sel==0) ? wq : (sel==1) ? wk : (sel==2) ? wv
                         : (sel==3) ? wg : wo;
        float v = src[rem];
        if (sel == 0) v *= 0.17677669529663687f * LOG2E;
        g_wt[sel*CZ*CZ + wfrag(o, c)] = f2tf32(v);
    } else {
        int wid  = (blockIdx.x - 320) * 8 + (threadIdx.x >> 5);
        int lane = threadIdx.x & 31;
        int h     = wid >> 9;
        int tile  = wid & 511;
        int mtile = tile >> 5;
        int jtile = tile & 31;
        int q0 = mtile*16 + (lane >> 2);
        int j0 = jtile*8  + (lane & 3);
        const float* tr = g_tri + (size_t)h*NPOS;
        float4 o;
        o.x = tr[(size_t)q0*NN + j0];
        o.y = tr[(size_t)q0*NN + j0 + 4];
        o.z = tr[(size_t)(q0+8)*NN + j0];
        o.w = tr[(size_t)(q0+8)*NN + j0 + 4];
        *(float4*)(g_trif + ((size_t)wid*32 + lane)*4) = o;
    }
}

// ---------------------------------------------------------------------------
// Hybrid tf32 GEMM (r13-verified).
// ---------------------------------------------------------------------------
#define ACHUNK 4096
#define WCHUNK 4096

__device__ __forceinline__ void gemm_stage(
    const uint32_t* __restrict__ A, const uint32_t* __restrict__ W,
    uint32_t* as, uint32_t* ws, int mt0, int c, int t)
{
    #pragma unroll
    for (int i = 0; i < 4; i++) {
        int idx = t + i*256;
        int tile = idx >> 5;
        int off  = (idx & 31) * 4;
        int mt = tile >> 2, ktl = tile & 3;
        cp16(as + tile*128 + off,
             A + ((size_t)(mt0+mt)*16 + c*4 + ktl)*128 + off);
    }
    #pragma unroll
    for (int i = 0; i < 4; i++) {
        int idx = t + i*256;
        int tile = idx >> 4;
        int off  = (idx & 15) * 4;
        int nt = tile >> 2, ktl = tile & 3;
        cp16(ws + tile*64 + off,
             W + ((size_t)nt*16 + c*4 + ktl)*64 + off);
    }
}

__device__ __forceinline__ void gemm2(
    const uint32_t* __restrict__ A,
    const uint32_t* __restrict__ W,
    int sel, int p0,
    const float* __restrict__ bias,
    float* __restrict__ outf)
{
    extern __shared__ uint32_t dyn[];
    int t    = threadIdx.x;
    int warp = t >> 5;
    int lane = t & 31;
    int gq   = lane >> 2, tq = lane & 3;
    int wm   = (warp >> 2) * 64;
    int wn   = (warp & 3) * 32;
    int wmt  = (warp >> 2) * 4;
    int wnt  = (warp & 3) * 4;
    int mt0  = p0 >> 4;

    float acc[4][4][4];
    #pragma unroll
    for (int mi = 0; mi < 4; mi++)
        #pragma unroll
        for (int ni = 0; ni < 4; ni++)
            #pragma unroll
            for (int r = 0; r < 4; r++) acc[mi][ni][r] = 0.0f;

    gemm_stage(A, W, dyn, dyn + 2*ACHUNK, mt0, 0, t);
    CP_COMMIT();
    CP_WAIT0();
    __syncthreads();

    for (int c = 0; c < 4; c++) {
        if (c < 3) {
            int nb = (c+1) & 1;
            gemm_stage(A, W, dyn + nb*ACHUNK, dyn + 2*ACHUNK + nb*WCHUNK,
                       mt0, c+1, t);
            CP_COMMIT();
        }
        const uint32_t* as = dyn + (c&1)*ACHUNK;
        const uint32_t* ws = dyn + 2*ACHUNK + (c&1)*WCHUNK;

        #pragma unroll
        for (int ktl = 0; ktl < 4; ktl++) {
            uint4 a4[4];
            uint2 b2[4];
            #pragma unroll
            for (int mi = 0; mi < 4; mi++)
                a4[mi] = *(const uint4*)(as + ((wmt+mi)*4 + ktl)*128 + lane*4);
            #pragma unroll
            for (int ni = 0; ni < 4; ni++)
                b2[ni] = *(const uint2*)(ws + ((wnt+ni)*4 + ktl)*64 + lane*2);
            #pragma unroll
            for (int mi = 0; mi < 4; mi++)
                #pragma unroll
                for (int ni = 0; ni < 4; ni++)
                    mma_tf32(acc[mi][ni], (const uint32_t*)&a4[mi],
                             (const uint32_t*)&b2[ni]);
        }
        if (c < 3) {
            CP_WAIT0();
            __syncthreads();
        }
    }

    #pragma unroll
    for (int mi = 0; mi < 4; mi++) {
        #pragma unroll
        for (int ni = 0; ni < 4; ni++) {
            int col = wn + ni*8 + tq*2;
            int r0  = p0 + wm + mi*16 + gq;
            if (sel <= 2) {
                uint32_t* outt = (sel==0) ? g_q : (sel==1) ? g_k : g_v;
                #pragma unroll
                for (int rr = 0; rr < 2; rr++) {
                    int pos = r0 + rr*8;
                    *(uint2*)(outt + (size_t)pos*CZ + col) =
                        make_uint2(f2tf32(acc[mi][ni][rr*2+0]),
                                   f2tf32(acc[mi][ni][rr*2+1]));
                }
            } else if (sel == 3) {
                float b0 = bias[col], b1 = bias[col+1];
                #pragma unroll
                for (int rr = 0; rr < 2; rr++) {
                    int pos = r0 + rr*8;
                    float vx = 1.0f/(1.0f + __expf(-(acc[mi][ni][rr*2+0] + b0)));
                    float vy = 1.0f/(1.0f + __expf(-(acc[mi][ni][rr*2+1] + b1)));
                    *(float2*)(g_g + (size_t)pos*CZ + col) = make_float2(vx, vy);
                }
            } else {
                float b0 = bias[col], b1 = bias[col+1];
                #pragma unroll
                for (int rr = 0; rr < 2; rr++) {
                    int pos = r0 + rr*8;
                    *(float2*)(outf + (size_t)pos*CZ + col) =
                        make_float2(acc[mi][ni][rr*2+0] + b0,
                                    acc[mi][ni][rr*2+1] + b1);
                }
            }
        }
    }
}

__global__ __launch_bounds__(256, 2) void k_proj(const float* __restrict__ bg)
{
    int sel = blockIdx.y;
    gemm2(g_xn, g_wt + sel*CZ*CZ, sel, blockIdx.x * 128, bg, nullptr);
}

__global__ __launch_bounds__(256, 2) void k_outp(
    const float* __restrict__ bo, float* __restrict__ out)
{
    gemm2(g_oa, g_wt + 4*CZ*CZ, 4, blockIdx.x * 128, bo, out);
}

// ---------------------------------------------------------------------------
// K3: attention (r15-verified core) — shuffle-free permuted-key PV.
// NEW: epilogue writes g_oa in A-frag layout directly (2x STG.64 per (mi,nd),
// same store count as row-major; consecutive-word pairing rowbit 0/1).
// ---------------------------------------------------------------------------
#define KVSTG (64*36)

__global__ __launch_bounds__(128, 4) void k_attn(const float* __restrict__ mask)
{
    __shared__ uint32_t kvbuf[4*KVSTG];
    __shared__ float mb_s[256];

    int i  = blockIdx.x;
    int q0 = blockIdx.y * 128;
    int h  = blockIdx.z;
    int t = threadIdx.x;
    int warp = t >> 5, lane = t & 31;
    int gq = lane >> 2, tq = lane & 3;
    int wrow = q0 + warp * 32;
    int pg = (gq & 1) ? (gq >> 1) + 4 : (gq >> 1);   // permuted key row

    mb_s[t]       = LOG2E * 1e9f * (mask[i*NN + t] - 1.0f);
    mb_s[t + 128] = LOG2E * 1e9f * (mask[i*NN + t + 128] - 1.0f);

    uint32_t* kb[2] = { kvbuf,           kvbuf + KVSTG };
    uint32_t* vb[2] = { kvbuf + 2*KVSTG, kvbuf + 3*KVSTG };

    #pragma unroll
    for (int it = 0; it < 4; it++) {
        int idx = t + it*128;
        int row = idx >> 3, c4 = idx & 7;
        size_t gb = ((size_t)(i*NN + row))*CZ + h*DH + c4*4;
        cp16(&kb[0][row*36 + c4*4], g_k + gb);
        cp16(&vb[0][row*36 + c4*4], g_v + gb);
    }
    CP_COMMIT();

    uint32_t qf[2][4][4];
    #pragma unroll
    for (int mi = 0; mi < 2; mi++) {
        const uint32_t* qr0 = g_q + ((size_t)(i*NN + wrow + mi*16 + gq))*CZ + h*DH;
        const uint32_t* qr8 = qr0 + 8*CZ;
        #pragma unroll
        for (int ks = 0; ks < 4; ks++) {
            qf[mi][ks][0] = qr0[ks*8 + tq];
            qf[mi][ks][1] = qr8[ks*8 + tq];
            qf[mi][ks][2] = qr0[ks*8 + tq + 4];
            qf[mi][ks][3] = qr8[ks*8 + tq + 4];
        }
    }

    float lrun[2][2] = {{0.f,0.f},{0.f,0.f}};
    float oacc[2][4][4];
    #pragma unroll
    for (int mi = 0; mi < 2; mi++)
        #pragma unroll
        for (int nd = 0; nd < 4; nd++)
            #pragma unroll
            for (int r = 0; r < 4; r++) oacc[mi][nd][r] = 0.0f;

    int mtile0 = wrow >> 4;
    const float4* tf = (const float4*)g_trif;

    CP_WAIT0();
    __syncthreads();

    for (int jb = 0; jb < 4; jb++) {
        int j0 = jb * 64;
        int cur = jb & 1;
        if (jb < 3) {
            int nxt = (jb+1) & 1;
            #pragma unroll
            for (int it = 0; it < 4; it++) {
                int idx = t + it*128;
                int row = idx >> 3, c4 = idx & 7;
                size_t gb = ((size_t)(i*NN + j0 + 64 + row))*CZ + h*DH + c4*4;
                cp16(&kb[nxt][row*36 + c4*4], g_k + gb);
                cp16(&vb[nxt][row*36 + c4*4], g_v + gb);
            }
            CP_COMMIT();
        }
        const uint32_t* k_s = kb[cur];
        const uint32_t* v_s = vb[cur];

        #pragma unroll
        for (int half = 0; half < 2; half++) {
            int jh = half * 32;

            // S = Q K^T with permuted key rows
            float sacc[2][4][4];
            #pragma unroll
            for (int mi = 0; mi < 2; mi++)
                #pragma unroll
                for (int ni = 0; ni < 4; ni++)
                    #pragma unroll
                    for (int r = 0; r < 4; r++) sacc[mi][ni][r] = 0.0f;

            #pragma unroll
            for (int ks = 0; ks < 4; ks++) {
                uint32_t bf[4][2];
                #pragma unroll
                for (int ni = 0; ni < 4; ni++) {
                    int base = (jh + ni*8 + pg)*36 + ks*8 + tq;
                    bf[ni][0] = k_s[base];
                    bf[ni][1] = k_s[base + 4];
                }
                #pragma unroll
                for (int mi = 0; mi < 2; mi++)
                    #pragma unroll
                    for (int ni = 0; ni < 4; ni++)
                        mma_tf32(sacc[mi][ni], qf[mi][ks], bf[ni]);
            }

            // p = ex2(sacc + tri + mb); acc cols are keys (tq, tq+4)
            #pragma unroll
            for (int mi = 0; mi < 2; mi++) {
                float la0 = 0.f, la1 = 0.f;
                #pragma unroll
                for (int ni = 0; ni < 4; ni++) {
                    int jtile = jb*8 + half*4 + ni;
                    float4 tv = tf[((h*16 + mtile0 + mi)*32 + jtile)*32 + lane];
                    int j = j0 + jh + ni*8 + tq;
                    float mb0 = mb_s[j], mb1 = mb_s[j+4];
                    float p0 = ex2f(sacc[mi][ni][0] + (tv.x + mb0));
                    float p1 = ex2f(sacc[mi][ni][1] + (tv.y + mb1));
                    float p2 = ex2f(sacc[mi][ni][2] + (tv.z + mb0));
                    float p3 = ex2f(sacc[mi][ni][3] + (tv.w + mb1));
                    uint32_t u0 = f2tf32(p0), u1 = f2tf32(p1);
                    uint32_t u2 = f2tf32(p2), u3 = f2tf32(p3);
                    sacc[mi][ni][0] = __uint_as_float(u0);
                    sacc[mi][ni][1] = __uint_as_float(u1);
                    sacc[mi][ni][2] = __uint_as_float(u2);
                    sacc[mi][ni][3] = __uint_as_float(u3);
                    la0 += __uint_as_float(u0) + __uint_as_float(u1);
                    la1 += __uint_as_float(u2) + __uint_as_float(u3);
                }
                lrun[mi][0] += la0; lrun[mi][1] += la1;
            }

            // O += P V : A-frag = {c0, c2, c1, c3} directly (no shuffles)
            #pragma unroll
            for (int ks2 = 0; ks2 < 4; ks2++) {
                uint32_t bf[4][2];
                #pragma unroll
                for (int nd = 0; nd < 4; nd++) {
                    bf[nd][0] = v_s[(jh + ks2*8 + tq)*36     + nd*8 + gq];
                    bf[nd][1] = v_s[(jh + ks2*8 + tq + 4)*36 + nd*8 + gq];
                }
                #pragma unroll
                for (int mi = 0; mi < 2; mi++) {
                    uint32_t af[4];
                    af[0] = __float_as_uint(sacc[mi][ks2][0]);
                    af[1] = __float_as_uint(sacc[mi][ks2][2]);
                    af[2] = __float_as_uint(sacc[mi][ks2][1]);
                    af[3] = __float_as_uint(sacc[mi][ks2][3]);
                    #pragma unroll
                    for (int nd = 0; nd < 4; nd++)
                        mma_tf32(oacc[mi][nd], af, bf[nd]);
                }
            }
        }
        if (jb < 3) {
            CP_WAIT0();
            __syncthreads();
        }
    }

    // epilogue: normalize, gate, store g_oa in A-frag layout directly.
    // (r,col) & (r+8,col) are consecutive words in the frag tile -> STG.64.
    #pragma unroll
    for (int mi = 0; mi < 2; mi++) {
        float l0 = lrun[mi][0];
        l0 += __shfl_xor_sync(0xffffffffu, l0, 1);
        l0 += __shfl_xor_sync(0xffffffffu, l0, 2);
        float l1 = lrun[mi][1];
        l1 += __shfl_xor_sync(0xffffffffu, l1, 1);
        l1 += __shfl_xor_sync(0xffffffffu, l1, 2);
        float inv0 = 1.0f / l0, inv1 = 1.0f / l1;
        int r0  = wrow + mi*16 + gq;
        int pos = i*NN + r0;
        int mt  = pos >> 4;
        #pragma unroll
        for (int nd = 0; nd < 4; nd++) {
            int col  = h*DH + nd*8 + tq*2;             // even col
            int tile = mt*16 + (col>>3);
            float2 gg0 = *(const float2*)(g_g + (size_t)pos*CZ + col);
            float2 gg1 = *(const float2*)(g_g + (size_t)(pos+8)*CZ + col);
            // even col: words (rowbit 0,1) at slot gq*4 + (col&3), colbit offset
            int idxE = (tile<<7) + ((gq*4 + (col&3))<<2) + (((col>>2)&1)<<1);
            int idxO = (tile<<7) + ((gq*4 + ((col+1)&3))<<2) + ((((col+1)>>2)&1)<<1);
            *(uint2*)(g_oa + idxE) = make_uint2(
                f2tf32(oacc[mi][nd][0]*inv0*gg0.x),
                f2tf32(oacc[mi][nd][2]*inv1*gg1.x));
            *(uint2*)(g_oa + idxO) = make_uint2(
                f2tf32(oacc[mi][nd][1]*inv0*gg0.y),
                f2tf32(oacc[mi][nd][3]*inv1*gg1.y));
        }
    }
}

// ---------------------------------------------------------------------------
extern "C" void kernel_launch(void* const* d_in, const int* in_sizes, int n_in,
                              void* d_out, int out_size)
{
    const float* x     = (const float*)d_in[0];
    const float* mask  = (const float*)d_in[1];
    const float* ln_g  = (const float*)d_in[2];
    const float* ln_b  = (const float*)d_in[3];
    const float* w_tri = (const float*)d_in[4];
    const float* wq    = (const float*)d_in[5];
    const float* wk    = (const float*)d_in[6];
    const float* wv    = (const float*)d_in[7];
    const float* wg    = (const float*)d_in[8];
    const float* bg    = (const float*)d_in[9];
    const float* wo    = (const float*)d_in[10];
    const float* bo    = (const float*)d_in[11];
    float* out = (float*)d_out;

    const int GEMM_SMEM = (2*ACHUNK + 2*WCHUNK) * 4;   // 65536 B
    cudaFuncSetAttribute(k_proj, cudaFuncAttributeMaxDynamicSharedMemorySize, GEMM_SMEM);
    cudaFuncSetAttribute(k_outp, cudaFuncAttributeMaxDynamicSharedMemorySize, GEMM_SMEM);

    k_ln  <<<NPOS/16, 512>>>(x, ln_g, ln_b, w_tri);
    k_aux <<<576, 256>>>(wq, wk, wv, wg, wo);
    k_proj<<<dim3(NPOS/128, 4), 256, GEMM_SMEM>>>(bg);
    k_attn<<<dim3(NN, 2, H), 128>>>(mask);
    k_outp<<<NPOS/128, 256, GEMM_SMEM>>>(bo, out);
}